// round 8
// baseline (speedup 1.0000x reference)
#include <cuda_runtime.h>

#define NBLK 444            // 148 SMs x 3 resident CTAs: exactly one wave
#define NTHR 256
#define STRIDE (NBLK * NTHR)

// Per-block partial sums (deterministic reduction, no data atomics).
__device__ float g_part_p[NBLK];
__device__ float g_part_ll[NBLK];
__device__ float g_part_np[NBLK];
__device__ unsigned g_ticket = 0;   // self-resetting last-block-done counter

__device__ __forceinline__ float frcp(float x) {
    float y;
    asm("rcp.approx.f32 %0, %1;" : "=f"(y) : "f"(x));
    return y;
}
__device__ __forceinline__ float fex2(float x) {
    float y;
    asm("ex2.approx.f32 %0, %1;" : "=f"(y) : "f"(x));
    return y;
}

struct Acc { float p, ll, np; };

// Per-iteration payload: 11 float2 (p, t, 3x{m,s,w}) = 22 regs per buffer.
struct V11 {
    float2 p, t;
    float2 m0, m1, m2;
    float2 s0, s1, s2;
    float2 w0, w1, w2;
};

// Binned mixture probability, log2-domain:
//   sigmoid(u)-sigmoid(l) = (el-eu)/((1+eu)(1+el)),
//   eu = 2^(a-b), el = 2^(a+b), a=(m-t)*inv*log2e, b=HB*inv*log2e.
// Saturation: overflow -> den inf -> rcp 0 -> 0/NaN; fmax(.,EPS)=EPS,
// matching the reference's clamped regime.
__device__ __forceinline__ float comp_prob(float m, float t, float s) {
    const float EPS = 1e-8f;
    const float HB  = 0.05f;
    const float L2E = 1.4426950408889634f;
    float il = frcp(s + EPS) * L2E;
    float a  = (m - t) * il;
    float b  = HB * il;
    float eu = fex2(a - b);
    float el = fex2(a + b);
    float den = frcp((1.f + eu) * (1.f + el));
    return fmaxf((el - eu) * den, EPS);
}

__device__ __forceinline__ void process_elem(
    float p, float t,
    float m0, float s0, float w0,
    float m1, float s1, float w1,
    float m2, float s2, float w2,
    Acc& a)
{
    const float EPS = 1e-8f;

    float lik = w0 * comp_prob(m0, t, s0);
    lik = fmaf(w1, comp_prob(m1, t, s1), lik);
    lik = fmaf(w2, comp_prob(m2, t, s2), lik);

    bool paid = (t > 0.f);
    float ll = __logf(lik + EPS);
    if (paid) { a.ll += ll; a.np += 1.f; }

    float q = paid ? p : (1.f - p);
    a.p -= fmaxf(__logf(q), -100.f);
}

__device__ __forceinline__ void load_v11(
    V11& b, int v, int nvec,
    const float2* __restrict__ pp2, const float2* __restrict__ tv2,
    const float2* __restrict__ mu2, const float2* __restrict__ sg2,
    const float2* __restrict__ wt2)
{
    b.p  = __ldg(pp2 + v);
    b.t  = __ldg(tv2 + v);
    b.m0 = __ldg(mu2 + v);
    b.m1 = __ldg(mu2 + nvec + v);
    b.m2 = __ldg(mu2 + 2 * nvec + v);
    b.s0 = __ldg(sg2 + v);
    b.s1 = __ldg(sg2 + nvec + v);
    b.s2 = __ldg(sg2 + 2 * nvec + v);
    b.w0 = __ldg(wt2 + v);
    b.w1 = __ldg(wt2 + nvec + v);
    b.w2 = __ldg(wt2 + 2 * nvec + v);
}

__device__ __forceinline__ void compute_v11(const V11& b, Acc& a)
{
    process_elem(b.p.x, b.t.x, b.m0.x, b.s0.x, b.w0.x,
                 b.m1.x, b.s1.x, b.w1.x, b.m2.x, b.s2.x, b.w2.x, a);
    process_elem(b.p.y, b.t.y, b.m0.y, b.s0.y, b.w0.y,
                 b.m1.y, b.s1.y, b.w1.y, b.m2.y, b.s2.y, b.w2.y, a);
}

__global__ void __launch_bounds__(NTHR, 3) zimol_fused(
    const float* __restrict__ pp, const float* __restrict__ mu,
    const float* __restrict__ sg, const float* __restrict__ wt,
    const float* __restrict__ tv, float* __restrict__ out, int B)
{
    const int nvec = B >> 1;            // float2 vectors per row
    Acc a = {0.f, 0.f, 0.f};

    const float2* pp2 = reinterpret_cast<const float2*>(pp);
    const float2* tv2 = reinterpret_cast<const float2*>(tv);
    const float2* mu2 = reinterpret_cast<const float2*>(mu);
    const float2* sg2 = reinterpret_cast<const float2*>(sg);
    const float2* wt2 = reinterpret_cast<const float2*>(wt);

    const int idx = blockIdx.x * NTHR + threadIdx.x;
    int n = (idx < nvec) ? (nvec - idx + STRIDE - 1) / STRIDE : 0;

    V11 bufA, bufB;
    if (n > 0) load_v11(bufA, idx, nvec, pp2, tv2, mu2, sg2, wt2);

    // Software pipeline: prefetch iteration i+1 while computing iteration i.
    int i = 0;
    #pragma unroll 2
    for (; i + 1 < n; i++) {
        int vn = idx + (i + 1) * STRIDE;
        if (i & 1) {
            load_v11(bufA, vn, nvec, pp2, tv2, mu2, sg2, wt2);
            compute_v11(bufB, a);
        } else {
            load_v11(bufB, vn, nvec, pp2, tv2, mu2, sg2, wt2);
            compute_v11(bufA, a);
        }
    }
    if (n > 0) {
        if (i & 1) compute_v11(bufB, a);
        else       compute_v11(bufA, a);
    }

    // Scalar tail (B odd) — robustness; no-op for B = 4M.
    int tail = B & 1;
    if (tail) {
        int base = nvec << 1;
        if (idx < tail) {
            int j = base + idx;
            process_elem(pp[j], tv[j],
                         mu[0 * B + j], sg[0 * B + j], wt[0 * B + j],
                         mu[1 * B + j], sg[1 * B + j], wt[1 * B + j],
                         mu[2 * B + j], sg[2 * B + j], wt[2 * B + j], a);
        }
    }

    // ---- Block reduction (all float, shuffle + tiny smem) ----
    #pragma unroll
    for (int o = 16; o > 0; o >>= 1) {
        a.p  += __shfl_down_sync(0xffffffffu, a.p,  o);
        a.ll += __shfl_down_sync(0xffffffffu, a.ll, o);
        a.np += __shfl_down_sync(0xffffffffu, a.np, o);
    }

    __shared__ float shp[8], shl[8], shn[8];
    __shared__ bool s_last;
    int wid  = threadIdx.x >> 5;
    int lane = threadIdx.x & 31;
    if (lane == 0) { shp[wid] = a.p; shl[wid] = a.ll; shn[wid] = a.np; }
    __syncthreads();

    if (threadIdx.x == 0) {
        float vp = 0.f, vl = 0.f, vn = 0.f;
        #pragma unroll
        for (int k = 0; k < 8; k++) { vp += shp[k]; vl += shl[k]; vn += shn[k]; }
        g_part_p[blockIdx.x]  = vp;
        g_part_ll[blockIdx.x] = vl;
        g_part_np[blockIdx.x] = vn;
        __threadfence();
        unsigned t = atomicAdd(&g_ticket, 1u);
        s_last = (t == (unsigned)(NBLK - 1));
        if (s_last) g_ticket = 0u;   // self-reset: deterministic across replays
    }
    __syncthreads();

    // ---- Last block finalizes (float, 444 partials) ----
    if (s_last) {
        float sp = 0.f, sl = 0.f, sn = 0.f;
        for (int k = threadIdx.x; k < NBLK; k += NTHR) {
            sp += g_part_p[k];
            sl += g_part_ll[k];
            sn += g_part_np[k];
        }
        #pragma unroll
        for (int o = 16; o > 0; o >>= 1) {
            sp += __shfl_down_sync(0xffffffffu, sp, o);
            sl += __shfl_down_sync(0xffffffffu, sl, o);
            sn += __shfl_down_sync(0xffffffffu, sn, o);
        }
        if (lane == 0) { shp[wid] = sp; shl[wid] = sl; shn[wid] = sn; }
        __syncthreads();
        if (threadIdx.x == 0) {
            float vp = 0.f, vl = 0.f, vn = 0.f;
            #pragma unroll
            for (int k = 0; k < 8; k++) { vp += shp[k]; vl += shl[k]; vn += shn[k]; }
            float purchase = vp / (float)B;
            float ltv = (vn > 0.f) ? -(vl / fmaxf(vn, 1.f)) : 0.f;
            out[0] = purchase + ltv;
        }
    }
}

extern "C" void kernel_launch(void* const* d_in, const int* in_sizes, int n_in,
                              void* d_out, int out_size)
{
    const float* pp = (const float*)d_in[0];  // predicted_purchase_prob (B,)
    const float* mu = (const float*)d_in[1];  // mu     (K,B)
    const float* sg = (const float*)d_in[2];  // sigma  (K,B)
    const float* wt = (const float*)d_in[3];  // weight (K,B)
    const float* tv = (const float*)d_in[4];  // true_values (B,)
    int B = in_sizes[0];

    zimol_fused<<<NBLK, NTHR>>>(pp, mu, sg, wt, tv, (float*)d_out, B);
}